// round 3
// baseline (speedup 1.0000x reference)
#include <cuda_runtime.h>
#include <cuda_bf16.h>
#include <cstdint>

// Problem constants (fixed by the dataset)
#define NN   100000      // nodes
#define EE   1600000     // edges
#define CAP  128         // adjacency bucket capacity per node

// ---------------- scratch (device globals; no allocation allowed) ----------
__device__ float g_h0[(size_t)NN * 128];   // x @ W1
__device__ float g_h1[(size_t)NN * 128];   // relu(mean-agg(h0))
__device__ float g_h2[(size_t)NN * 64];    // h1 @ W2
__device__ int   g_deg[NN];
__device__ int   g_adj[(size_t)NN * CAP];
// W transposed to [n][k], split into bf16 hi/lo
__device__ __nv_bfloat16 g_w1hi[128 * 128];
__device__ __nv_bfloat16 g_w1lo[128 * 128];
__device__ __nv_bfloat16 g_w2hi[64 * 128];
__device__ __nv_bfloat16 g_w2lo[64 * 128];

// ---------------- adjacency build ------------------------------------------
__global__ void k_clear_deg() {
    int i = blockIdx.x * blockDim.x + threadIdx.x;
    if (i < NN) g_deg[i] = 0;
}

__global__ void k_build_adj(const int* __restrict__ erow,
                            const int* __restrict__ ecol) {
    int e = blockIdx.x * blockDim.x + threadIdx.x;
    if (e >= EE) return;
    int r = erow[e];
    int c = ecol[e];
    int pos = atomicAdd(&g_deg[r], 1);
    if (pos < CAP) g_adj[(size_t)r * CAP + pos] = c;
}

// ---------------- W prep: transpose [k][n] -> [n][k], bf16 hi/lo split ------
__global__ void k_prep_w(const float* __restrict__ W, __nv_bfloat16* __restrict__ hi,
                         __nv_bfloat16* __restrict__ lo, int K, int Ncol) {
    int i = blockIdx.x * blockDim.x + threadIdx.x;
    if (i >= K * Ncol) return;
    int k = i / Ncol;
    int n = i % Ncol;
    float w = W[i];
    __nv_bfloat16 h = __float2bfloat16_rn(w);
    float l = w - __bfloat162float(h);
    hi[n * K + k] = h;
    lo[n * K + k] = __float2bfloat16_rn(l);
}

// ---------------- bf16 mma.sync GEMM ----------------------------------------
// C[nrows, NCOL] = A[nrows, 128] @ W[128, NCOL]
// A fp32 row-major, split into bf16 hi/lo in smem; B prepped [n][k] bf16 hi/lo.
// 3-pass split: Ah*Bh + Ah*Bl + Al*Bh, fp32 accumulation (mma.m16n8k16).
// CTA: 256 threads = 8 warps (4 M x 2 N). CTA tile: 128 x NCOL, full K resident.
#define A_ROW_B 272   // 128 bf16 * 2B + 16B pad (bank-conflict-free fragments)

template <int NCOL>
__global__ __launch_bounds__(256, 1)
void k_gemm_mma(const float* __restrict__ A,
                const __nv_bfloat16* __restrict__ Bhi,
                const __nv_bfloat16* __restrict__ Blo,
                float* __restrict__ C, int nrows) {
    constexpr int K = 128;
    constexpr int WN = NCOL / 2;     // warp N extent
    constexpr int NT = WN / 8;       // n8 tiles per warp
    constexpr int A_BYTES = 128 * A_ROW_B;        // one plane
    constexpr int B_BYTES = NCOL * A_ROW_B;       // one plane

    extern __shared__ char smem[];
    char* sAhi = smem;
    char* sAlo = smem + A_BYTES;
    char* sBhi = sAlo + A_BYTES;
    char* sBlo = sBhi + B_BYTES;

    const int tid = threadIdx.x;
    const int r0 = blockIdx.x * 128;

    // ---- stage A: fp32 -> bf16 hi/lo, padded rows --------------------------
    for (int i = tid; i < 128 * 32; i += 256) {
        int m = i >> 5;
        int q = i & 31;                       // float4 index within row
        float4 v = make_float4(0.f, 0.f, 0.f, 0.f);
        int gr = r0 + m;
        if (gr < nrows)
            v = *reinterpret_cast<const float4*>(A + (size_t)gr * K + q * 4);
        __nv_bfloat162 h01, h23, l01, l23;
        __nv_bfloat16 hx = __float2bfloat16_rn(v.x);
        __nv_bfloat16 hy = __float2bfloat16_rn(v.y);
        __nv_bfloat16 hz = __float2bfloat16_rn(v.z);
        __nv_bfloat16 hw = __float2bfloat16_rn(v.w);
        h01.x = hx; h01.y = hy; h23.x = hz; h23.y = hw;
        l01.x = __float2bfloat16_rn(v.x - __bfloat162float(hx));
        l01.y = __float2bfloat16_rn(v.y - __bfloat162float(hy));
        l23.x = __float2bfloat16_rn(v.z - __bfloat162float(hz));
        l23.y = __float2bfloat16_rn(v.w - __bfloat162float(hw));
        __nv_bfloat162* ph = reinterpret_cast<__nv_bfloat162*>(sAhi + m * A_ROW_B);
        __nv_bfloat162* pl = reinterpret_cast<__nv_bfloat162*>(sAlo + m * A_ROW_B);
        ph[q * 2] = h01; ph[q * 2 + 1] = h23;
        pl[q * 2] = l01; pl[q * 2 + 1] = l23;
    }

    // ---- stage B: bf16 [n][k] -> padded rows --------------------------------
    for (int i = tid; i < NCOL * 16; i += 256) {
        int n = i >> 4;
        int q = i & 15;                       // uint4 (8 bf16) chunk within row
        uint4 vh = reinterpret_cast<const uint4*>(Bhi + n * K)[q];
        uint4 vl = reinterpret_cast<const uint4*>(Blo + n * K)[q];
        *reinterpret_cast<uint4*>(sBhi + n * A_ROW_B + q * 16) = vh;
        *reinterpret_cast<uint4*>(sBlo + n * A_ROW_B + q * 16) = vl;
    }
    __syncthreads();

    // ---- MMA mainloop -------------------------------------------------------
    const int lane = tid & 31;
    const int wid = tid >> 5;
    const int g = lane >> 2;
    const int tg = lane & 3;
    const int wm = wid & 3;            // 4 warps along M
    const int wn = wid >> 2;           // 2 warps along N
    const int mbase = wm * 32;
    const int nbase = wn * WN;

    float acc[2][NT][4];
#pragma unroll
    for (int mt = 0; mt < 2; mt++)
#pragma unroll
        for (int nt = 0; nt < NT; nt++)
#pragma unroll
            for (int j = 0; j < 4; j++) acc[mt][nt][j] = 0.0f;

#pragma unroll
    for (int ks = 0; ks < 8; ks++) {
        const int k0 = ks * 16;
        uint32_t ah[2][4], al[2][4];
#pragma unroll
        for (int mt = 0; mt < 2; mt++) {
            const char* ph = sAhi + (mbase + mt * 16 + g) * A_ROW_B + (k0 + tg * 2) * 2;
            const char* pl = sAlo + (mbase + mt * 16 + g) * A_ROW_B + (k0 + tg * 2) * 2;
            ah[mt][0] = *reinterpret_cast<const uint32_t*>(ph);
            ah[mt][1] = *reinterpret_cast<const uint32_t*>(ph + 8 * A_ROW_B);
            ah[mt][2] = *reinterpret_cast<const uint32_t*>(ph + 16);
            ah[mt][3] = *reinterpret_cast<const uint32_t*>(ph + 8 * A_ROW_B + 16);
            al[mt][0] = *reinterpret_cast<const uint32_t*>(pl);
            al[mt][1] = *reinterpret_cast<const uint32_t*>(pl + 8 * A_ROW_B);
            al[mt][2] = *reinterpret_cast<const uint32_t*>(pl + 16);
            al[mt][3] = *reinterpret_cast<const uint32_t*>(pl + 8 * A_ROW_B + 16);
        }
#pragma unroll
        for (int nt = 0; nt < NT; nt++) {
            const char* pbh = sBhi + (nbase + nt * 8 + g) * A_ROW_B + (k0 + tg * 2) * 2;
            const char* pbl = sBlo + (nbase + nt * 8 + g) * A_ROW_B + (k0 + tg * 2) * 2;
            uint32_t bh0 = *reinterpret_cast<const uint32_t*>(pbh);
            uint32_t bh1 = *reinterpret_cast<const uint32_t*>(pbh + 16);
            uint32_t bl0 = *reinterpret_cast<const uint32_t*>(pbl);
            uint32_t bl1 = *reinterpret_cast<const uint32_t*>(pbl + 16);
#pragma unroll
            for (int mt = 0; mt < 2; mt++) {
                asm volatile(
                    "mma.sync.aligned.m16n8k16.row.col.f32.bf16.bf16.f32 "
                    "{%0,%1,%2,%3}, {%4,%5,%6,%7}, {%8,%9}, {%0,%1,%2,%3};"
                    : "+f"(acc[mt][nt][0]), "+f"(acc[mt][nt][1]),
                      "+f"(acc[mt][nt][2]), "+f"(acc[mt][nt][3])
                    : "r"(ah[mt][0]), "r"(ah[mt][1]), "r"(ah[mt][2]), "r"(ah[mt][3]),
                      "r"(bh0), "r"(bh1));
                asm volatile(
                    "mma.sync.aligned.m16n8k16.row.col.f32.bf16.bf16.f32 "
                    "{%0,%1,%2,%3}, {%4,%5,%6,%7}, {%8,%9}, {%0,%1,%2,%3};"
                    : "+f"(acc[mt][nt][0]), "+f"(acc[mt][nt][1]),
                      "+f"(acc[mt][nt][2]), "+f"(acc[mt][nt][3])
                    : "r"(ah[mt][0]), "r"(ah[mt][1]), "r"(ah[mt][2]), "r"(ah[mt][3]),
                      "r"(bl0), "r"(bl1));
                asm volatile(
                    "mma.sync.aligned.m16n8k16.row.col.f32.bf16.bf16.f32 "
                    "{%0,%1,%2,%3}, {%4,%5,%6,%7}, {%8,%9}, {%0,%1,%2,%3};"
                    : "+f"(acc[mt][nt][0]), "+f"(acc[mt][nt][1]),
                      "+f"(acc[mt][nt][2]), "+f"(acc[mt][nt][3])
                    : "r"(al[mt][0]), "r"(al[mt][1]), "r"(al[mt][2]), "r"(al[mt][3]),
                      "r"(bh0), "r"(bh1));
            }
        }
    }

    // ---- epilogue -----------------------------------------------------------
#pragma unroll
    for (int mt = 0; mt < 2; mt++) {
#pragma unroll
        for (int nt = 0; nt < NT; nt++) {
            int r1 = r0 + mbase + mt * 16 + g;
            int r2 = r1 + 8;
            int cc = nbase + nt * 8 + tg * 2;
            if (r1 < nrows) {
                float2 v = make_float2(acc[mt][nt][0], acc[mt][nt][1]);
                *reinterpret_cast<float2*>(C + (size_t)r1 * NCOL + cc) = v;
            }
            if (r2 < nrows) {
                float2 v = make_float2(acc[mt][nt][2], acc[mt][nt][3]);
                *reinterpret_cast<float2*>(C + (size_t)r2 * NCOL + cc) = v;
            }
        }
    }
}

// ---------------- mean aggregation: warp per node ---------------------------
template <int D, bool RELU>
__global__ void k_agg(const float* __restrict__ src, float* __restrict__ dst) {
    constexpr int VEC = D / 32;
    const int gw = (blockIdx.x * blockDim.x + threadIdx.x) >> 5;
    if (gw >= NN) return;
    const int lane = threadIdx.x & 31;

    const int d = g_deg[gw];
    const int cnt = d < CAP ? d : CAP;
    const int* __restrict__ adj = g_adj + (size_t)gw * CAP;

    float acc[VEC];
#pragma unroll
    for (int v = 0; v < VEC; v++) acc[v] = 0.0f;

#pragma unroll 4
    for (int t = 0; t < cnt; t++) {
        int j = __ldg(&adj[t]);
        const float* p = src + (size_t)j * D + lane * VEC;
        if (VEC == 4) {
            float4 v = *reinterpret_cast<const float4*>(p);
            acc[0] += v.x; acc[1] += v.y; acc[2] += v.z; acc[3] += v.w;
        } else {
            float2 v = *reinterpret_cast<const float2*>(p);
            acc[0] += v.x; acc[1] += v.y;
        }
    }

    const float inv = 1.0f / (float)d;
    float* q = dst + (size_t)gw * D + lane * VEC;
    if (VEC == 4) {
        float4 o;
        o.x = acc[0] * inv; o.y = acc[1] * inv;
        o.z = acc[2] * inv; o.w = acc[3] * inv;
        if (RELU) {
            o.x = fmaxf(o.x, 0.f); o.y = fmaxf(o.y, 0.f);
            o.z = fmaxf(o.z, 0.f); o.w = fmaxf(o.w, 0.f);
        }
        *reinterpret_cast<float4*>(q) = o;
    } else {
        float2 o;
        o.x = acc[0] * inv; o.y = acc[1] * inv;
        if (RELU) { o.x = fmaxf(o.x, 0.f); o.y = fmaxf(o.y, 0.f); }
        *reinterpret_cast<float2*>(q) = o;
    }
}

// ---------------- launch -----------------------------------------------------
extern "C" void kernel_launch(void* const* d_in, const int* in_sizes, int n_in,
                              void* d_out, int out_size) {
    const float* x    = (const float*)d_in[0];
    const float* W1   = (const float*)d_in[1];
    const float* W2   = (const float*)d_in[2];
    const int*   erow = (const int*)d_in[3];
    const int*   ecol = (const int*)d_in[4];
    float* out = (float*)d_out;

    float *h0, *h1, *h2;
    __nv_bfloat16 *w1hi, *w1lo, *w2hi, *w2lo;
    cudaGetSymbolAddress((void**)&h0, g_h0);
    cudaGetSymbolAddress((void**)&h1, g_h1);
    cudaGetSymbolAddress((void**)&h2, g_h2);
    cudaGetSymbolAddress((void**)&w1hi, g_w1hi);
    cudaGetSymbolAddress((void**)&w1lo, g_w1lo);
    cudaGetSymbolAddress((void**)&w2hi, g_w2hi);
    cudaGetSymbolAddress((void**)&w2lo, g_w2lo);

    // dynamic smem: 2 A planes (128 rows x 272B) + 2 B planes (NCOL rows x 272B)
    const int SMEM1 = 2 * 128 * A_ROW_B + 2 * 128 * A_ROW_B;  // 139264
    const int SMEM2 = 2 * 128 * A_ROW_B + 2 * 64 * A_ROW_B;   // 104448
    cudaFuncSetAttribute(k_gemm_mma<128>, cudaFuncAttributeMaxDynamicSharedMemorySize, SMEM1);
    cudaFuncSetAttribute(k_gemm_mma<64>,  cudaFuncAttributeMaxDynamicSharedMemorySize, SMEM2);

    // prep weights (tiny)
    k_prep_w<<<(128 * 128 + 255) / 256, 256>>>(W1, w1hi, w1lo, 128, 128);
    k_prep_w<<<(128 * 64 + 255) / 256, 256>>>(W2, w2hi, w2lo, 128, 64);

    // adjacency
    k_clear_deg<<<(NN + 255) / 256, 256>>>();
    k_build_adj<<<(EE + 255) / 256, 256>>>(erow, ecol);

    const int NBLK = (NN + 127) / 128;  // 782

    // layer 1: h0 = x @ W1 ; h1 = relu(mean_agg(h0))
    k_gemm_mma<128><<<NBLK, 256, SMEM1>>>(x, w1hi, w1lo, h0, NN);
    k_agg<128, true><<<(NN * 32 + 255) / 256, 256>>>(h0, h1);

    // layer 2: h2 = h1 @ W2 ; out = mean_agg(h2)
    k_gemm_mma<64><<<NBLK, 256, SMEM2>>>(h1, w2hi, w2lo, h2, NN);
    k_agg<64, false><<<(NN * 32 + 255) / 256, 256>>>(h2, out);
}

// round 4
// speedup vs baseline: 1.3679x; 1.3679x over previous
#include <cuda_runtime.h>
#include <cuda_bf16.h>
#include <cstdint>

// Problem constants (fixed by the dataset)
#define NN   100000      // nodes
#define EE   1600000     // edges
#define CAP  128         // adjacency bucket capacity per node

// ---------------- scratch (device globals; no allocation allowed) ----------
__device__ float g_h0[(size_t)NN * 128];   // x @ W1
__device__ float g_h1[(size_t)NN * 128];   // relu(mean-agg(h0))
__device__ float g_h2[(size_t)NN * 64];    // h1 @ W2
__device__ int   g_deg[NN];
__device__ int   g_adj[(size_t)NN * CAP];
// W transposed to [n][k], split into bf16 hi/lo
__device__ __nv_bfloat16 g_w1hi[128 * 128];
__device__ __nv_bfloat16 g_w1lo[128 * 128];
__device__ __nv_bfloat16 g_w2hi[64 * 128];
__device__ __nv_bfloat16 g_w2lo[64 * 128];

#define A_ROW_B 272   // 128 bf16 * 2B + 16B pad (conflict-free fragment LDS)

// ---------------- adjacency build ------------------------------------------
__global__ void k_clear_deg() {
    int i = blockIdx.x * blockDim.x + threadIdx.x;
    if (i < NN) g_deg[i] = 0;
}

// 4 edges per thread: 4 independent atomic chains in flight (latency-bound op)
__global__ void k_build_adj(const int* __restrict__ erow,
                            const int* __restrict__ ecol) {
    int e0 = (blockIdx.x * blockDim.x + threadIdx.x) * 4;
    if (e0 >= EE) return;
    int4 r = *reinterpret_cast<const int4*>(erow + e0);
    int4 c = *reinterpret_cast<const int4*>(ecol + e0);
    int p0 = atomicAdd(&g_deg[r.x], 1);
    int p1 = atomicAdd(&g_deg[r.y], 1);
    int p2 = atomicAdd(&g_deg[r.z], 1);
    int p3 = atomicAdd(&g_deg[r.w], 1);
    if (p0 < CAP) g_adj[(size_t)r.x * CAP + p0] = c.x;
    if (p1 < CAP) g_adj[(size_t)r.y * CAP + p1] = c.y;
    if (p2 < CAP) g_adj[(size_t)r.z * CAP + p2] = c.z;
    if (p3 < CAP) g_adj[(size_t)r.w * CAP + p3] = c.w;
}

// ---------------- W prep (both weights, one launch) --------------------------
// transpose [k][n] -> [n][k], bf16 hi/lo Dekker split
__global__ void k_prep_w(const float* __restrict__ W1, const float* __restrict__ W2,
                         __nv_bfloat16* __restrict__ w1hi, __nv_bfloat16* __restrict__ w1lo,
                         __nv_bfloat16* __restrict__ w2hi, __nv_bfloat16* __restrict__ w2lo) {
    int i = blockIdx.x * blockDim.x + threadIdx.x;
    if (i < 128 * 128) {
        int k = i / 128, n = i % 128;
        float w = W1[i];
        __nv_bfloat16 h = __float2bfloat16_rn(w);
        w1hi[n * 128 + k] = h;
        w1lo[n * 128 + k] = __float2bfloat16_rn(w - __bfloat162float(h));
    } else if (i < 128 * 128 + 128 * 64) {
        int j = i - 128 * 128;
        int k = j / 64, n = j % 64;
        float w = W2[j];
        __nv_bfloat16 h = __float2bfloat16_rn(w);
        w2hi[n * 128 + k] = h;
        w2lo[n * 128 + k] = __float2bfloat16_rn(w - __bfloat162float(h));
    }
}

// ---------------- persistent bf16 mma.sync GEMM ------------------------------
// C[nrows, NCOL] = A[nrows, 128] @ W[128, NCOL]
// B (hi/lo, [n][k]) staged in smem ONCE per CTA; loop over 64-row M tiles.
// 3-pass Dekker split: Ah*Bh + Ah*Bl + Al*Bh, fp32 accumulation.
// 8 warps = 2(M) x 4(N); warp tile 32 x (NCOL/4).
template <int NCOL>
__global__ __launch_bounds__(256, 2)
void k_gemm_mma(const float* __restrict__ A,
                const __nv_bfloat16* __restrict__ Bhi,
                const __nv_bfloat16* __restrict__ Blo,
                float* __restrict__ C, int nrows) {
    constexpr int K = 128;
    constexpr int WN = NCOL / 4;     // warp N extent
    constexpr int NT = WN / 8;       // n8 tiles per warp
    constexpr int B_BYTES = NCOL * A_ROW_B;
    constexpr int A_BYTES = 64 * A_ROW_B;

    extern __shared__ char smem[];
    char* sBhi = smem;
    char* sBlo = smem + B_BYTES;
    char* sAhi = sBlo + B_BYTES;
    char* sAlo = sAhi + A_BYTES;

    const int tid = threadIdx.x;
    const int lane = tid & 31;
    const int wid = tid >> 5;
    const int g = lane >> 2;
    const int tg = lane & 3;
    const int mbase = (wid & 1) * 32;
    const int nbase = (wid >> 1) * WN;

    // ---- stage B hi/lo once -------------------------------------------------
    for (int i = tid; i < NCOL * 16; i += 256) {
        int n = i >> 4;
        int q = i & 15;   // uint4 (8 bf16) chunk along K
        *reinterpret_cast<uint4*>(sBhi + n * A_ROW_B + q * 16) =
            reinterpret_cast<const uint4*>(Bhi + n * K)[q];
        *reinterpret_cast<uint4*>(sBlo + n * A_ROW_B + q * 16) =
            reinterpret_cast<const uint4*>(Blo + n * K)[q];
    }

    const int ntiles = (nrows + 63) / 64;
    for (int t = blockIdx.x; t < ntiles; t += gridDim.x) {
        const int r0 = t * 64;
        __syncthreads();  // prior tile's A reads done (and B staged, first iter)

        // ---- stage A tile: fp32 -> bf16 hi/lo --------------------------------
#pragma unroll
        for (int it = 0; it < 8; it++) {
            int i = tid + it * 256;
            int m = i >> 5;
            int q = i & 31;    // float4 index along K
            float4 v = make_float4(0.f, 0.f, 0.f, 0.f);
            int gr = r0 + m;
            if (gr < nrows)
                v = *reinterpret_cast<const float4*>(A + (size_t)gr * K + q * 4);
            __nv_bfloat162 h01 = __float22bfloat162_rn(make_float2(v.x, v.y));
            __nv_bfloat162 h23 = __float22bfloat162_rn(make_float2(v.z, v.w));
            float2 f01 = __bfloat1622float2(h01);
            float2 f23 = __bfloat1622float2(h23);
            __nv_bfloat162 l01 = __float22bfloat162_rn(make_float2(v.x - f01.x, v.y - f01.y));
            __nv_bfloat162 l23 = __float22bfloat162_rn(make_float2(v.z - f23.x, v.w - f23.y));
            uint2 hh = make_uint2(*reinterpret_cast<uint32_t*>(&h01),
                                  *reinterpret_cast<uint32_t*>(&h23));
            uint2 ll = make_uint2(*reinterpret_cast<uint32_t*>(&l01),
                                  *reinterpret_cast<uint32_t*>(&l23));
            *reinterpret_cast<uint2*>(sAhi + m * A_ROW_B + q * 8) = hh;
            *reinterpret_cast<uint2*>(sAlo + m * A_ROW_B + q * 8) = ll;
        }
        __syncthreads();

        // ---- MMA mainloop ----------------------------------------------------
        float acc[2][NT][4];
#pragma unroll
        for (int mt = 0; mt < 2; mt++)
#pragma unroll
            for (int nt = 0; nt < NT; nt++)
#pragma unroll
                for (int j = 0; j < 4; j++) acc[mt][nt][j] = 0.0f;

#pragma unroll
        for (int ks = 0; ks < 8; ks++) {
            const int k0 = ks * 16;
            uint32_t ah[2][4], al[2][4];
#pragma unroll
            for (int mt = 0; mt < 2; mt++) {
                const char* ph = sAhi + (mbase + mt * 16 + g) * A_ROW_B + (k0 + tg * 2) * 2;
                const char* pl = sAlo + (mbase + mt * 16 + g) * A_ROW_B + (k0 + tg * 2) * 2;
                ah[mt][0] = *reinterpret_cast<const uint32_t*>(ph);
                ah[mt][1] = *reinterpret_cast<const uint32_t*>(ph + 8 * A_ROW_B);
                ah[mt][2] = *reinterpret_cast<const uint32_t*>(ph + 16);
                ah[mt][3] = *reinterpret_cast<const uint32_t*>(ph + 8 * A_ROW_B + 16);
                al[mt][0] = *reinterpret_cast<const uint32_t*>(pl);
                al[mt][1] = *reinterpret_cast<const uint32_t*>(pl + 8 * A_ROW_B);
                al[mt][2] = *reinterpret_cast<const uint32_t*>(pl + 16);
                al[mt][3] = *reinterpret_cast<const uint32_t*>(pl + 8 * A_ROW_B + 16);
            }
#pragma unroll
            for (int nt = 0; nt < NT; nt++) {
                const char* pbh = sBhi + (nbase + nt * 8 + g) * A_ROW_B + (k0 + tg * 2) * 2;
                const char* pbl = sBlo + (nbase + nt * 8 + g) * A_ROW_B + (k0 + tg * 2) * 2;
                uint32_t bh0 = *reinterpret_cast<const uint32_t*>(pbh);
                uint32_t bh1 = *reinterpret_cast<const uint32_t*>(pbh + 16);
                uint32_t bl0 = *reinterpret_cast<const uint32_t*>(pbl);
                uint32_t bl1 = *reinterpret_cast<const uint32_t*>(pbl + 16);
#pragma unroll
                for (int mt = 0; mt < 2; mt++) {
                    asm volatile(
                        "mma.sync.aligned.m16n8k16.row.col.f32.bf16.bf16.f32 "
                        "{%0,%1,%2,%3}, {%4,%5,%6,%7}, {%8,%9}, {%0,%1,%2,%3};"
                        : "+f"(acc[mt][nt][0]), "+f"(acc[mt][nt][1]),
                          "+f"(acc[mt][nt][2]), "+f"(acc[mt][nt][3])
                        : "r"(ah[mt][0]), "r"(ah[mt][1]), "r"(ah[mt][2]), "r"(ah[mt][3]),
                          "r"(bh0), "r"(bh1));
                    asm volatile(
                        "mma.sync.aligned.m16n8k16.row.col.f32.bf16.bf16.f32 "
                        "{%0,%1,%2,%3}, {%4,%5,%6,%7}, {%8,%9}, {%0,%1,%2,%3};"
                        : "+f"(acc[mt][nt][0]), "+f"(acc[mt][nt][1]),
                          "+f"(acc[mt][nt][2]), "+f"(acc[mt][nt][3])
                        : "r"(ah[mt][0]), "r"(ah[mt][1]), "r"(ah[mt][2]), "r"(ah[mt][3]),
                          "r"(bl0), "r"(bl1));
                    asm volatile(
                        "mma.sync.aligned.m16n8k16.row.col.f32.bf16.bf16.f32 "
                        "{%0,%1,%2,%3}, {%4,%5,%6,%7}, {%8,%9}, {%0,%1,%2,%3};"
                        : "+f"(acc[mt][nt][0]), "+f"(acc[mt][nt][1]),
                          "+f"(acc[mt][nt][2]), "+f"(acc[mt][nt][3])
                        : "r"(al[mt][0]), "r"(al[mt][1]), "r"(al[mt][2]), "r"(al[mt][3]),
                          "r"(bh0), "r"(bh1));
                }
            }
        }

        // ---- epilogue ---------------------------------------------------------
#pragma unroll
        for (int mt = 0; mt < 2; mt++) {
#pragma unroll
            for (int nt = 0; nt < NT; nt++) {
                int r1 = r0 + mbase + mt * 16 + g;
                int r2 = r1 + 8;
                int cc = nbase + nt * 8 + tg * 2;
                if (r1 < nrows)
                    *reinterpret_cast<float2*>(C + (size_t)r1 * NCOL + cc) =
                        make_float2(acc[mt][nt][0], acc[mt][nt][1]);
                if (r2 < nrows)
                    *reinterpret_cast<float2*>(C + (size_t)r2 * NCOL + cc) =
                        make_float2(acc[mt][nt][2], acc[mt][nt][3]);
            }
        }
    }
}

// ---------------- mean aggregation: warp per node ---------------------------
template <int D, bool RELU>
__global__ void k_agg(const float* __restrict__ src, float* __restrict__ dst) {
    constexpr int VEC = D / 32;
    const int gw = (blockIdx.x * blockDim.x + threadIdx.x) >> 5;
    if (gw >= NN) return;
    const int lane = threadIdx.x & 31;

    const int d = g_deg[gw];
    const int cnt = d < CAP ? d : CAP;
    const int* __restrict__ adj = g_adj + (size_t)gw * CAP;

    float acc[VEC];
#pragma unroll
    for (int v = 0; v < VEC; v++) acc[v] = 0.0f;

#pragma unroll 4
    for (int t = 0; t < cnt; t++) {
        int j = __ldg(&adj[t]);
        const float* p = src + (size_t)j * D + lane * VEC;
        if (VEC == 4) {
            float4 v = *reinterpret_cast<const float4*>(p);
            acc[0] += v.x; acc[1] += v.y; acc[2] += v.z; acc[3] += v.w;
        } else {
            float2 v = *reinterpret_cast<const float2*>(p);
            acc[0] += v.x; acc[1] += v.y;
        }
    }

    const float inv = 1.0f / (float)d;
    float* q = dst + (size_t)gw * D + lane * VEC;
    if (VEC == 4) {
        float4 o;
        o.x = acc[0] * inv; o.y = acc[1] * inv;
        o.z = acc[2] * inv; o.w = acc[3] * inv;
        if (RELU) {
            o.x = fmaxf(o.x, 0.f); o.y = fmaxf(o.y, 0.f);
            o.z = fmaxf(o.z, 0.f); o.w = fmaxf(o.w, 0.f);
        }
        *reinterpret_cast<float4*>(q) = o;
    } else {
        float2 o;
        o.x = acc[0] * inv; o.y = acc[1] * inv;
        if (RELU) { o.x = fmaxf(o.x, 0.f); o.y = fmaxf(o.y, 0.f); }
        *reinterpret_cast<float2*>(q) = o;
    }
}

// ---------------- launch -----------------------------------------------------
extern "C" void kernel_launch(void* const* d_in, const int* in_sizes, int n_in,
                              void* d_out, int out_size) {
    const float* x    = (const float*)d_in[0];
    const float* W1   = (const float*)d_in[1];
    const float* W2   = (const float*)d_in[2];
    const int*   erow = (const int*)d_in[3];
    const int*   ecol = (const int*)d_in[4];
    float* out = (float*)d_out;

    float *h0, *h1, *h2;
    __nv_bfloat16 *w1hi, *w1lo, *w2hi, *w2lo;
    cudaGetSymbolAddress((void**)&h0, g_h0);
    cudaGetSymbolAddress((void**)&h1, g_h1);
    cudaGetSymbolAddress((void**)&h2, g_h2);
    cudaGetSymbolAddress((void**)&w1hi, g_w1hi);
    cudaGetSymbolAddress((void**)&w1lo, g_w1lo);
    cudaGetSymbolAddress((void**)&w2hi, g_w2hi);
    cudaGetSymbolAddress((void**)&w2lo, g_w2lo);

    // smem: B hi/lo (NCOL rows) + A hi/lo (64 rows), all rows A_ROW_B bytes
    const int SMEM1 = 2 * 128 * A_ROW_B + 2 * 64 * A_ROW_B;  // 104448 -> 2 CTA/SM
    const int SMEM2 = 2 * 64 * A_ROW_B + 2 * 64 * A_ROW_B;   //  69632 -> 3 CTA/SM
    cudaFuncSetAttribute(k_gemm_mma<128>, cudaFuncAttributeMaxDynamicSharedMemorySize, SMEM1);
    cudaFuncSetAttribute(k_gemm_mma<64>,  cudaFuncAttributeMaxDynamicSharedMemorySize, SMEM2);

    // launch order puts gemm1 in profiler slot #4
    k_clear_deg<<<(NN + 255) / 256, 256>>>();                                   // 1
    k_prep_w<<<(128 * 128 + 128 * 64 + 255) / 256, 256>>>(W1, W2, w1hi, w1lo,
                                                          w2hi, w2lo);          // 2
    k_build_adj<<<(EE / 4 + 255) / 256, 256>>>(erow, ecol);                      // 3

    k_gemm_mma<128><<<2 * 148, 256, SMEM1>>>(x, w1hi, w1lo, h0, NN);             // 4
    k_agg<128, true><<<(NN * 32 + 255) / 256, 256>>>(h0, h1);                    // 5
    k_gemm_mma<64><<<3 * 148, 256, SMEM2>>>(h1, w2hi, w2lo, h2, NN);             // 6
    k_agg<64, false><<<(NN * 32 + 255) / 256, 256>>>(h2, out);                   // 7
}

// round 5
// speedup vs baseline: 1.4845x; 1.0852x over previous
#include <cuda_runtime.h>
#include <cuda_bf16.h>
#include <cuda_fp16.h>
#include <cstdint>

// Problem constants (fixed by the dataset)
#define NN   100000      // nodes
#define EE   1600000     // edges
#define CAP  128         // adjacency bucket capacity per node

// ---------------- scratch (device globals; no allocation allowed) ----------
__device__ __half g_h0[(size_t)NN * 128];  // x @ W1            (fp16)
__device__ float  g_h1[(size_t)NN * 128];  // relu(mean-agg h0) (fp32)
__device__ __half g_h2[(size_t)NN * 64];   // h1 @ W2           (fp16)
__device__ int    g_deg[NN];
__device__ int    g_adj[(size_t)NN * CAP];
// W transposed to [n][k], split into bf16 hi/lo
__device__ __nv_bfloat16 g_w1hi[128 * 128];
__device__ __nv_bfloat16 g_w1lo[128 * 128];
__device__ __nv_bfloat16 g_w2hi[64 * 128];
__device__ __nv_bfloat16 g_w2lo[64 * 128];

#define A_ROW_B 272   // 128 bf16 * 2B + 16B pad (conflict-free ldmatrix rows)

// ---------------- prep: weights hi/lo transpose + clear degrees -------------
__global__ void k_prep_clear(const float* __restrict__ W1, const float* __restrict__ W2,
                             __nv_bfloat16* __restrict__ w1hi, __nv_bfloat16* __restrict__ w1lo,
                             __nv_bfloat16* __restrict__ w2hi, __nv_bfloat16* __restrict__ w2lo) {
    int i = blockIdx.x * blockDim.x + threadIdx.x;
    if (i < NN) g_deg[i] = 0;
    if (i < 128 * 128) {
        int k = i / 128, n = i % 128;
        float w = W1[i];
        __nv_bfloat16 h = __float2bfloat16_rn(w);
        w1hi[n * 128 + k] = h;
        w1lo[n * 128 + k] = __float2bfloat16_rn(w - __bfloat162float(h));
    } else if (i < 128 * 128 + 128 * 64) {
        int j = i - 128 * 128;
        int k = j / 64, n = j % 64;
        float w = W2[j];
        __nv_bfloat16 h = __float2bfloat16_rn(w);
        w2hi[n * 128 + k] = h;
        w2lo[n * 128 + k] = __float2bfloat16_rn(w - __bfloat162float(h));
    }
}

// 4 edges per thread: 4 independent atomic chains in flight
__global__ void k_build_adj(const int* __restrict__ erow,
                            const int* __restrict__ ecol) {
    int e0 = (blockIdx.x * blockDim.x + threadIdx.x) * 4;
    if (e0 >= EE) return;
    int4 r = *reinterpret_cast<const int4*>(erow + e0);
    int4 c = *reinterpret_cast<const int4*>(ecol + e0);
    int p0 = atomicAdd(&g_deg[r.x], 1);
    int p1 = atomicAdd(&g_deg[r.y], 1);
    int p2 = atomicAdd(&g_deg[r.z], 1);
    int p3 = atomicAdd(&g_deg[r.w], 1);
    if (p0 < CAP) g_adj[(size_t)r.x * CAP + p0] = c.x;
    if (p1 < CAP) g_adj[(size_t)r.y * CAP + p1] = c.y;
    if (p2 < CAP) g_adj[(size_t)r.z * CAP + p2] = c.z;
    if (p3 < CAP) g_adj[(size_t)r.w * CAP + p3] = c.w;
}

// ---------------- ldmatrix helpers -------------------------------------------
#define LDMX4(r0, r1, r2, r3, addr) \
    asm volatile("ldmatrix.sync.aligned.m8n8.x4.shared.b16 {%0,%1,%2,%3}, [%4];" \
                 : "=r"(r0), "=r"(r1), "=r"(r2), "=r"(r3) : "r"(addr))
#define LDMX2(r0, r1, addr) \
    asm volatile("ldmatrix.sync.aligned.m8n8.x2.shared.b16 {%0,%1}, [%2];" \
                 : "=r"(r0), "=r"(r1) : "r"(addr))
#define MMA_BF16(acc, a, b0, b1) \
    asm volatile("mma.sync.aligned.m16n8k16.row.col.f32.bf16.bf16.f32 " \
                 "{%0,%1,%2,%3}, {%4,%5,%6,%7}, {%8,%9}, {%0,%1,%2,%3};" \
                 : "+f"(acc[0]), "+f"(acc[1]), "+f"(acc[2]), "+f"(acc[3]) \
                 : "r"(a[0]), "r"(a[1]), "r"(a[2]), "r"(a[3]), "r"(b0), "r"(b1))

// ---------------- persistent bf16 mma.sync GEMM ------------------------------
// C[nrows, NCOL](fp16) = A[nrows, 128](fp32) @ W[128, NCOL]
// B hi/lo staged once; per-tile A staged as bf16 hi/lo; 3-pass Dekker split.
// 8 warps = 2(M) x 4(N); warp tile 32 x (NCOL/4).
template <int NCOL>
__global__ __launch_bounds__(256, 2)
void k_gemm_mma(const float* __restrict__ A,
                const __nv_bfloat16* __restrict__ Bhi,
                const __nv_bfloat16* __restrict__ Blo,
                __half* __restrict__ C, int nrows) {
    constexpr int K = 128;
    constexpr int WN = NCOL / 4;
    constexpr int NT = WN / 8;
    constexpr int B_BYTES = NCOL * A_ROW_B;
    constexpr int A_BYTES = 64 * A_ROW_B;

    extern __shared__ char smem[];
    char* sBhi = smem;
    char* sBlo = smem + B_BYTES;
    char* sAhi = sBlo + B_BYTES;
    char* sAlo = sAhi + A_BYTES;

    const int tid = threadIdx.x;
    const int lane = tid & 31;
    const int wid = tid >> 5;
    const int g = lane >> 2;
    const int tg = lane & 3;
    const int mbase = (wid & 1) * 32;
    const int nbase = (wid >> 1) * WN;

    // ---- stage B hi/lo once --------------------------------------------------
    for (int i = tid; i < NCOL * 16; i += 256) {
        int n = i >> 4;
        int q = i & 15;
        *reinterpret_cast<uint4*>(sBhi + n * A_ROW_B + q * 16) =
            reinterpret_cast<const uint4*>(Bhi + n * K)[q];
        *reinterpret_cast<uint4*>(sBlo + n * A_ROW_B + q * 16) =
            reinterpret_cast<const uint4*>(Blo + n * K)[q];
    }

    // ---- precompute ldmatrix smem addresses (fixed across tiles) --------------
    // A (x4): matrix q = lane>>3: row += (q&1)*8, col += (q>>1)*16B
    const int rlm = lane & 7;
    const int qa = lane >> 3;
    uint32_t aAhi[2], aAlo[2];
#pragma unroll
    for (int mt = 0; mt < 2; mt++) {
        int row = mbase + mt * 16 + (qa & 1) * 8 + rlm;
        int col = (qa >> 1) * 16;
        aAhi[mt] = (uint32_t)__cvta_generic_to_shared(sAhi) + row * A_ROW_B + col;
        aAlo[mt] = (uint32_t)__cvta_generic_to_shared(sAlo) + row * A_ROW_B + col;
    }
    // B (x2): lanes 0-15: matrix q2 = (lane>>3)&1: col += q2*16B
    const int lb = lane & 15;
    uint32_t aBhi[NT], aBlo[NT];
#pragma unroll
    for (int nt = 0; nt < NT; nt++) {
        int row = nbase + nt * 8 + (lb & 7);
        int col = ((lb >> 3) & 1) * 16;
        aBhi[nt] = (uint32_t)__cvta_generic_to_shared(sBhi) + row * A_ROW_B + col;
        aBlo[nt] = (uint32_t)__cvta_generic_to_shared(sBlo) + row * A_ROW_B + col;
    }

    const int ntiles = (nrows + 63) / 64;
    for (int t = blockIdx.x; t < ntiles; t += gridDim.x) {
        const int r0 = t * 64;
        __syncthreads();  // prior tile's A reads done (and B staged, first iter)

        // ---- stage A tile: fp32 -> bf16 hi/lo ---------------------------------
#pragma unroll
        for (int it = 0; it < 8; it++) {
            int i = tid + it * 256;
            int m = i >> 5;
            int q = i & 31;
            float4 v = make_float4(0.f, 0.f, 0.f, 0.f);
            int gr = r0 + m;
            if (gr < nrows)
                v = *reinterpret_cast<const float4*>(A + (size_t)gr * K + q * 4);
            __nv_bfloat162 h01 = __float22bfloat162_rn(make_float2(v.x, v.y));
            __nv_bfloat162 h23 = __float22bfloat162_rn(make_float2(v.z, v.w));
            float2 f01 = __bfloat1622float2(h01);
            float2 f23 = __bfloat1622float2(h23);
            __nv_bfloat162 l01 = __float22bfloat162_rn(make_float2(v.x - f01.x, v.y - f01.y));
            __nv_bfloat162 l23 = __float22bfloat162_rn(make_float2(v.z - f23.x, v.w - f23.y));
            uint2 hh = make_uint2(*reinterpret_cast<uint32_t*>(&h01),
                                  *reinterpret_cast<uint32_t*>(&h23));
            uint2 ll = make_uint2(*reinterpret_cast<uint32_t*>(&l01),
                                  *reinterpret_cast<uint32_t*>(&l23));
            *reinterpret_cast<uint2*>(sAhi + m * A_ROW_B + q * 8) = hh;
            *reinterpret_cast<uint2*>(sAlo + m * A_ROW_B + q * 8) = ll;
        }
        __syncthreads();

        // ---- MMA mainloop ------------------------------------------------------
        float acc[2][NT][4];
#pragma unroll
        for (int mt = 0; mt < 2; mt++)
#pragma unroll
            for (int nt = 0; nt < NT; nt++)
#pragma unroll
                for (int j = 0; j < 4; j++) acc[mt][nt][j] = 0.0f;

#pragma unroll
        for (int ks = 0; ks < 8; ks++) {
            const uint32_t ko = ks * 32;  // 16 halves = 32 bytes per k-step
            uint32_t ah[2][4], al[2][4];
#pragma unroll
            for (int mt = 0; mt < 2; mt++) {
                LDMX4(ah[mt][0], ah[mt][1], ah[mt][2], ah[mt][3], aAhi[mt] + ko);
                LDMX4(al[mt][0], al[mt][1], al[mt][2], al[mt][3], aAlo[mt] + ko);
            }
#pragma unroll
            for (int nt = 0; nt < NT; nt++) {
                uint32_t bh0, bh1, bl0, bl1;
                LDMX2(bh0, bh1, aBhi[nt] + ko);
                LDMX2(bl0, bl1, aBlo[nt] + ko);
#pragma unroll
                for (int mt = 0; mt < 2; mt++) {
                    MMA_BF16(acc[mt][nt], ah[mt], bh0, bh1);
                    MMA_BF16(acc[mt][nt], ah[mt], bl0, bl1);
                    MMA_BF16(acc[mt][nt], al[mt], bh0, bh1);
                }
            }
        }

        // ---- epilogue: fp32 acc -> fp16 out -------------------------------------
#pragma unroll
        for (int mt = 0; mt < 2; mt++) {
#pragma unroll
            for (int nt = 0; nt < NT; nt++) {
                int r1 = r0 + mbase + mt * 16 + g;
                int r2 = r1 + 8;
                int cc = nbase + nt * 8 + tg * 2;
                if (r1 < nrows)
                    *reinterpret_cast<__half2*>(C + (size_t)r1 * NCOL + cc) =
                        __floats2half2_rn(acc[mt][nt][0], acc[mt][nt][1]);
                if (r2 < nrows)
                    *reinterpret_cast<__half2*>(C + (size_t)r2 * NCOL + cc) =
                        __floats2half2_rn(acc[mt][nt][2], acc[mt][nt][3]);
            }
        }
    }
}

// ---------------- mean aggregation: warp per node, fp16 in / fp32 out --------
template <int D, bool RELU>
__global__ void k_agg_h(const __half* __restrict__ src, float* __restrict__ dst) {
    constexpr int VEC = D / 32;   // halves per lane (4 or 2)
    const int gw = (blockIdx.x * blockDim.x + threadIdx.x) >> 5;
    if (gw >= NN) return;
    const int lane = threadIdx.x & 31;

    const int d = g_deg[gw];
    const int cnt = d < CAP ? d : CAP;
    const int* __restrict__ adj = g_adj + (size_t)gw * CAP;

    float acc[VEC];
#pragma unroll
    for (int v = 0; v < VEC; v++) acc[v] = 0.0f;

#pragma unroll 4
    for (int t = 0; t < cnt; t++) {
        int j = __ldg(&adj[t]);
        const __half* p = src + (size_t)j * D + lane * VEC;
        if (VEC == 4) {
            uint2 v = *reinterpret_cast<const uint2*>(p);
            float2 f0 = __half22float2(*reinterpret_cast<__half2*>(&v.x));
            float2 f1 = __half22float2(*reinterpret_cast<__half2*>(&v.y));
            acc[0] += f0.x; acc[1] += f0.y; acc[2] += f1.x; acc[3] += f1.y;
        } else {
            uint32_t v = *reinterpret_cast<const uint32_t*>(p);
            float2 f0 = __half22float2(*reinterpret_cast<__half2*>(&v));
            acc[0] += f0.x; acc[1] += f0.y;
        }
    }

    const float inv = 1.0f / (float)d;
    float* q = dst + (size_t)gw * D + lane * VEC;
    if (VEC == 4) {
        float4 o;
        o.x = acc[0] * inv; o.y = acc[1] * inv;
        o.z = acc[2] * inv; o.w = acc[3] * inv;
        if (RELU) {
            o.x = fmaxf(o.x, 0.f); o.y = fmaxf(o.y, 0.f);
            o.z = fmaxf(o.z, 0.f); o.w = fmaxf(o.w, 0.f);
        }
        *reinterpret_cast<float4*>(q) = o;
    } else {
        float2 o;
        o.x = acc[0] * inv; o.y = acc[1] * inv;
        if (RELU) { o.x = fmaxf(o.x, 0.f); o.y = fmaxf(o.y, 0.f); }
        *reinterpret_cast<float2*>(q) = o;
    }
}

// ---------------- launch -------------------------------------------------------
extern "C" void kernel_launch(void* const* d_in, const int* in_sizes, int n_in,
                              void* d_out, int out_size) {
    const float* x    = (const float*)d_in[0];
    const float* W1   = (const float*)d_in[1];
    const float* W2   = (const float*)d_in[2];
    const int*   erow = (const int*)d_in[3];
    const int*   ecol = (const int*)d_in[4];
    float* out = (float*)d_out;

    __half *h0, *h2;
    float* h1;
    __nv_bfloat16 *w1hi, *w1lo, *w2hi, *w2lo;
    cudaGetSymbolAddress((void**)&h0, g_h0);
    cudaGetSymbolAddress((void**)&h1, g_h1);
    cudaGetSymbolAddress((void**)&h2, g_h2);
    cudaGetSymbolAddress((void**)&w1hi, g_w1hi);
    cudaGetSymbolAddress((void**)&w1lo, g_w1lo);
    cudaGetSymbolAddress((void**)&w2hi, g_w2hi);
    cudaGetSymbolAddress((void**)&w2lo, g_w2lo);

    const int SMEM1 = 2 * 128 * A_ROW_B + 2 * 64 * A_ROW_B;  // 104448 -> 2 CTA/SM
    const int SMEM2 = 2 * 64 * A_ROW_B + 2 * 64 * A_ROW_B;   //  69632
    cudaFuncSetAttribute(k_gemm_mma<128>, cudaFuncAttributeMaxDynamicSharedMemorySize, SMEM1);
    cudaFuncSetAttribute(k_gemm_mma<64>,  cudaFuncAttributeMaxDynamicSharedMemorySize, SMEM2);

    // launch order puts agg1 in profiler slot #4
    k_prep_clear<<<(NN + 255) / 256, 256>>>(W1, W2, w1hi, w1lo, w2hi, w2lo);     // 1
    k_build_adj<<<(EE / 4 + 255) / 256, 256>>>(erow, ecol);                       // 2
    k_gemm_mma<128><<<2 * 148, 256, SMEM1>>>(x, w1hi, w1lo, h0, NN);              // 3
    k_agg_h<128, true><<<(NN * 32 + 255) / 256, 256>>>(h0, h1);                   // 4
    k_gemm_mma<64><<<3 * 148, 256, SMEM2>>>(h1, w2hi, w2lo, h2, NN);              // 5
    k_agg_h<64, false><<<(NN * 32 + 255) / 256, 256>>>(h2, out);                  // 6
}